// round 16
// baseline (speedup 1.0000x reference)
#include <cuda_runtime.h>

// -------------------------------------------------------------------------
// MaskedBilinearFullSymLoss — B=16, C=2, H=W=512, scalar f32 output.
// Persistent single-wave kernel (888 blocks = 6/SM x 148), static sync-free
// unit assignment. FINE-GRAINED units: 2-row strips (4096 units) => tail
// imbalance 8% instead of 23%. Thread = 2 consecutive cols => 4 px/unit.
// err linear in channels: H = sy*g0 + sx*g1 combined at load.
// -------------------------------------------------------------------------

#define HH 512
#define WW 512
#define NPERSIST 888u

__device__ double g_acc;            // zero-initialized
__device__ unsigned int g_ticket;   // zero-initialized

__device__ __forceinline__ float2 ld2(const float* __restrict__ p) {
    return *(const float2*)p;
}

struct Ctx {
    const float* __restrict__ g0;
    const float* __restrict__ g1;
    const float* __restrict__ mk;
    float wx1, wx2, wy1, wy2, w11, w12, w21, w22, sy, sx;
    int dx1, dy1, dy2, imax, jmax, i0, j0;
};

// 3-float shifted window [ja, ja+1, ja+2]; P = ja parity. Clamped values are
// only consumed with a zero validity factor.
template<int P>
__device__ __forceinline__ void ldwin(const float* __restrict__ row, int ja,
                                      float& x0, float& x1, float& x2) {
    if (P == 0) {
        float2 v = ld2(row + min(ja, WW - 2));
        float  s = row[min(ja + 2, WW - 1)];
        x0 = v.x; x1 = v.y; x2 = s;
    } else {
        float2 a = ld2(row + min(ja - 1, WW - 2));
        float2 b = ld2(row + min(ja + 1, WW - 2));
        x0 = a.y; x1 = b.x; x2 = b.y;
    }
}

// 2-float window [c, c+1]; Q = c parity.
template<int Q>
__device__ __forceinline__ void ldpair(const float* __restrict__ row, int c,
                                       float& y0, float& y1) {
    if (Q == 0) {
        float2 v = ld2(row + min(c, WW - 2));
        y0 = v.x; y1 = v.y;
    } else {
        y0 = row[min(c,     WW - 1)];
        y1 = row[min(c + 1, WW - 1)];
    }
}

// ---- positive branch: 2 output rows i0..i0+1, cols (j0, j0+1) ----
template<int P>
__device__ __forceinline__ float pos_duo(const Ctx& c) {
    const int ja = c.j0 + c.dx1;

    // 3 shared shifted rows, channel-combined: H = sy*g0 + sx*g1
    float H0[3], H1[3], H2[3];
    #pragma unroll
    for (int t = 0; t < 3; t++) {
        const int os = min(c.i0 + c.dy1 + t, HH - 1) * WW;
        float x0, x1, x2, y0, y1, y2;
        ldwin<P>(c.g0 + os, ja, x0, x1, x2);
        ldwin<P>(c.g1 + os, ja, y0, y1, y2);
        H0[t] = c.sy * x0 + c.sx * y0;
        H1[t] = c.sy * x1 + c.sx * y1;
        H2[t] = c.sy * x2 + c.sx * y2;
    }

    const float jv0 = (c.j0     < c.jmax) ? 1.0f : 0.0f;
    const float jv1 = (c.j0 + 1 < c.jmax) ? 1.0f : 0.0f;

    float acc = 0.0f;
    #pragma unroll
    for (int r = 0; r < 2; r++) {
        const int oc = (c.i0 + r) * WW + c.j0;     // always in-bounds
        float2 c0 = ld2(c.g0 + oc);
        float2 c1 = ld2(c.g1 + oc);
        float2 mm = ld2(c.mk + oc);
        const float rvv = (c.i0 + r < c.imax) ? 1.0f : 0.0f;
        mm.x *= rvv * jv0;
        mm.y *= rvv * jv1;
        float hcx = c.sy * c0.x + c.sx * c1.x;
        float hcy = c.sy * c0.y + c.sx * c1.y;
        float s0 = c.w11 * H0[r] + c.w12 * H1[r]
                 + c.w21 * H0[r+1] + c.w22 * H1[r+1];
        float e0 = hcx - s0;
        acc += mm.x * e0 * e0;
        float s1 = c.w11 * H1[r] + c.w12 * H2[r]
                 + c.w21 * H1[r+1] + c.w22 * H2[r+1];
        float e1 = hcy - s1;
        acc += mm.y * e1 * e1;
    }
    return acc;
}

// ---- negative branch: 2 output rows i0..i0+1, cols (j0, j0+1) ----
template<int Q>
__device__ __forceinline__ float neg_duo(const Ctx& c) {
    const int m2  = -c.dx1;            // >= 0
    const int cB0 = c.j0 + m2;

    // 3 shared second-term rows at cols (cB0, cB0+1), channel-combined
    float Sa[3], Sb[3];
    #pragma unroll
    for (int t = 0; t < 3; t++) {
        const int os = min(c.i0 + t, HH - 1) * WW;
        float a0, b0, a1, b1;
        ldpair<Q>(c.g0 + os, cB0, a0, b0);
        ldpair<Q>(c.g1 + os, cB0, a1, b1);
        Sa[t] = c.sy * a0 + c.sx * a1;
        Sb[t] = c.sy * b0 + c.sx * b1;
    }

    const float jv0 = (c.j0     < c.jmax) ? 1.0f : 0.0f;
    const float jv1 = (c.j0 + 1 < c.jmax) ? 1.0f : 0.0f;

    float acc = 0.0f;
    #pragma unroll
    for (int r = 0; r < 2; r++) {
        const int of = min(c.i0 + c.dy2 + r, HH - 1) * WW;
        float2 v0 = ld2(c.g0 + of + c.j0);
        float2 v1 = ld2(c.g1 + of + c.j0);
        float z0 = c.g0[of + min(c.j0 + 2, WW - 1)];
        float z1 = c.g1[of + min(c.j0 + 2, WW - 1)];
        float mx, my;
        ldpair<Q>(c.mk + of, cB0, mx, my);
        const float rvv = (c.i0 + r < c.imax) ? 1.0f : 0.0f;
        mx *= rvv * jv0;
        my *= rvv * jv1;
        float Hx = c.sy * v0.x + c.sx * v1.x;
        float Hy = c.sy * v0.y + c.sx * v1.y;
        float Hz = c.sy * z0   + c.sx * z1;
        float f0 = c.wx1 * Hx + c.wx2 * Hy;
        float s0 = c.wy1 * Sa[r+1] + c.wy2 * Sa[r];
        float e0 = f0 - s0;
        acc += mx * e0 * e0;
        float f1 = c.wx1 * Hy + c.wx2 * Hz;
        float s1 = c.wy1 * Sb[r+1] + c.wy2 * Sb[r];
        float e1 = f1 - s1;
        acc += my * e1 * e1;
    }
    return acc;
}

__global__ __launch_bounds__(256, 6)
void loss_kernel(const float* __restrict__ grid,
                 const float* __restrict__ gt,
                 const float* __restrict__ gd,
                 const float* __restrict__ mask,
                 int B, unsigned int units, float* __restrict__ out)
{
    const int H = HH, W = WW;
    const int tid = threadIdx.x;

    __shared__ float wsum[8];

    float facc = 0.0f;

    // static assignment; warps proceed fully independently (no shared state)
    for (unsigned int u = blockIdx.x; u < units; u += gridDim.x) {
        const int b  = (int)(u >> 8);         // 256 strips per batch item
        const int i0 = (int)(u & 255u) * 2;

        const float dx = -8.0f * gt[2 * b + 0];
        const float dy =  8.0f * gt[2 * b + 1];

        Ctx c;
        c.sx = gd[2 * b + 0];
        c.sy = gd[2 * b + 1];
        const float dx1f = floorf(dx), dy1f = floorf(dy);
        c.dx1 = (int)dx1f;  c.dy1 = (int)dy1f;  c.dy2 = c.dy1 + 1;
        const int dx2 = c.dx1 + 1;
        c.wx1 = (dx1f + 1.0f) - dx;  c.wx2 = dx - dx1f;
        c.wy1 = (dy1f + 1.0f) - dy;  c.wy2 = dy - dy1f;
        c.w11 = c.wy1 * c.wx1;  c.w12 = c.wy1 * c.wx2;
        c.w21 = c.wy2 * c.wx1;  c.w22 = c.wy2 * c.wx2;
        c.g0 = grid + (size_t)(2 * b + 0) * H * W;
        c.g1 = grid + (size_t)(2 * b + 1) * H * W;
        c.mk = mask + (size_t)b * H * W;
        c.imax = H - c.dy2;
        c.i0 = i0;
        c.j0 = 2 * tid;

        float uacc;
        float cnt;
        if (dx > 0.0f) {
            c.jmax = W - dx2;
            cnt = (float)c.imax * (float)c.jmax;
            if (c.dx1 & 1) uacc = pos_duo<1>(c);
            else           uacc = pos_duo<0>(c);
        } else {
            c.jmax = W + c.dx1;
            cnt = (float)c.imax * (float)c.jmax;
            if ((-c.dx1) & 1) uacc = neg_duo<1>(c);
            else              uacc = neg_duo<0>(c);
        }
        facc += __fdividef(uacc, cnt);
    }

    // ---- block reduction (8 warps)
    #pragma unroll
    for (int o = 16; o > 0; o >>= 1)
        facc += __shfl_down_sync(0xFFFFFFFFu, facc, o);

    const int lane = tid & 31;
    const int warp = tid >> 5;
    if (lane == 0) wsum[warp] = facc;
    __syncthreads();

    if (tid == 0) {
        float s = 0.0f;
        #pragma unroll
        for (int k = 0; k < 8; k++) s += wsum[k];
        atomicAdd(&g_acc, (double)s);

        __threadfence();
        unsigned int prev = atomicInc(&g_ticket, (unsigned int)gridDim.x - 1u);
        if (prev == (unsigned int)gridDim.x - 1u) {
            double total = atomicAdd(&g_acc, 0.0);    // atomic read
            out[0] = (float)(total / (double)B);
            g_acc  = 0.0;                             // reset for next replay
            __threadfence();
        }
    }
}

extern "C" void kernel_launch(void* const* d_in, const int* in_sizes, int n_in,
                              void* d_out, int out_size)
{
    const float* grid = (const float*)d_in[0];
    const float* gt   = (const float*)d_in[1];
    const float* gd   = (const float*)d_in[2];
    const float* mask = (const float*)d_in[3];
    float* out = (float*)d_out;

    const int B = in_sizes[1] / 2;            // gt_sym_axis is (B, 2)
    const unsigned int units = (unsigned int)(256 * B);

    loss_kernel<<<NPERSIST, 256>>>(grid, gt, gd, mask, B, units, out);
}

// round 17
// speedup vs baseline: 1.0677x; 1.0677x over previous
#include <cuda_runtime.h>

// -------------------------------------------------------------------------
// MaskedBilinearFullSymLoss — B=16, C=2, H=W=512, scalar f32 output.
// Persistent single-wave kernel (740 blocks = 5/SM x 148), static sync-free
// unit assignment. Unit = batch b x 4-row strip; thread = 2 cols => 8 px.
// ALL unit loads (window rows + center/mask) front-batched before any
// compute: one exposed latency per unit, ~27 outstanding loads/thread.
// err linear in channels: H = sy*g0 + sx*g1 combined at load.
// -------------------------------------------------------------------------

#define HH 512
#define WW 512
#define NPERSIST 740u

__device__ double g_acc;            // zero-initialized
__device__ unsigned int g_ticket;   // zero-initialized

__device__ __forceinline__ float2 ld2(const float* __restrict__ p) {
    return *(const float2*)p;
}

struct Ctx {
    const float* __restrict__ g0;
    const float* __restrict__ g1;
    const float* __restrict__ mk;
    float wx1, wx2, wy1, wy2, w11, w12, w21, w22, sy, sx;
    int dx1, dy1, dy2, imax, jmax, i0, j0;
};

// 3-float shifted window [ja, ja+1, ja+2]; P = ja parity. Clamped values are
// only consumed with a zero validity factor.
template<int P>
__device__ __forceinline__ void ldwin(const float* __restrict__ row, int ja,
                                      float& x0, float& x1, float& x2) {
    if (P == 0) {
        float2 v = ld2(row + min(ja, WW - 2));
        float  s = row[min(ja + 2, WW - 1)];
        x0 = v.x; x1 = v.y; x2 = s;
    } else {
        float2 a = ld2(row + min(ja - 1, WW - 2));
        float2 b = ld2(row + min(ja + 1, WW - 2));
        x0 = a.y; x1 = b.x; x2 = b.y;
    }
}

// 2-float window [c, c+1]; Q = c parity.
template<int Q>
__device__ __forceinline__ void ldpair(const float* __restrict__ row, int c,
                                       float& y0, float& y1) {
    if (Q == 0) {
        float2 v = ld2(row + min(c, WW - 2));
        y0 = v.x; y1 = v.y;
    } else {
        y0 = row[min(c,     WW - 1)];
        y1 = row[min(c + 1, WW - 1)];
    }
}

// ---- positive branch: 4 output rows i0..i0+3, cols (j0, j0+1) ----
template<int P>
__device__ __forceinline__ float pos_quad(const Ctx& c) {
    const int ja = c.j0 + c.dx1;

    // ---- front batch 1: 5 shifted window rows, channel-combined
    float H0[5], H1[5], H2[5];
    #pragma unroll
    for (int t = 0; t < 5; t++) {
        const int os = min(c.i0 + c.dy1 + t, HH - 1) * WW;
        float x0, x1, x2, y0, y1, y2;
        ldwin<P>(c.g0 + os, ja, x0, x1, x2);
        ldwin<P>(c.g1 + os, ja, y0, y1, y2);
        H0[t] = c.sy * x0 + c.sx * y0;
        H1[t] = c.sy * x1 + c.sx * y1;
        H2[t] = c.sy * x2 + c.sx * y2;
    }

    // ---- front batch 2: all center/mask loads for the 4 rows
    float2 c0[4], c1[4], mm[4];
    #pragma unroll
    for (int r = 0; r < 4; r++) {
        const int oc = (c.i0 + r) * WW + c.j0;     // always in-bounds
        c0[r] = ld2(c.g0 + oc);
        c1[r] = ld2(c.g1 + oc);
        mm[r] = ld2(c.mk + oc);
    }

    const float jv0 = (c.j0     < c.jmax) ? 1.0f : 0.0f;
    const float jv1 = (c.j0 + 1 < c.jmax) ? 1.0f : 0.0f;

    // ---- compute: no memory dependence left
    float acc = 0.0f;
    #pragma unroll
    for (int r = 0; r < 4; r++) {
        const float rvv = (c.i0 + r < c.imax) ? 1.0f : 0.0f;
        const float wmx = mm[r].x * rvv * jv0;
        const float wmy = mm[r].y * rvv * jv1;
        float hcx = c.sy * c0[r].x + c.sx * c1[r].x;
        float hcy = c.sy * c0[r].y + c.sx * c1[r].y;
        float s0 = c.w11 * H0[r] + c.w12 * H1[r]
                 + c.w21 * H0[r+1] + c.w22 * H1[r+1];
        float e0 = hcx - s0;
        acc += wmx * e0 * e0;
        float s1 = c.w11 * H1[r] + c.w12 * H2[r]
                 + c.w21 * H1[r+1] + c.w22 * H2[r+1];
        float e1 = hcy - s1;
        acc += wmy * e1 * e1;
    }
    return acc;
}

// ---- negative branch: 4 output rows i0..i0+3, cols (j0, j0+1) ----
template<int Q>
__device__ __forceinline__ float neg_quad(const Ctx& c) {
    const int m2  = -c.dx1;            // >= 0
    const int cB0 = c.j0 + m2;

    // ---- front batch 1: 5 shared second-term rows + 4 mask pairs
    float Sa[5], Sb[5];
    #pragma unroll
    for (int t = 0; t < 5; t++) {
        const int os = min(c.i0 + t, HH - 1) * WW;
        float a0, b0, a1, b1;
        ldpair<Q>(c.g0 + os, cB0, a0, b0);
        ldpair<Q>(c.g1 + os, cB0, a1, b1);
        Sa[t] = c.sy * a0 + c.sx * a1;
        Sb[t] = c.sy * b0 + c.sx * b1;
    }
    float MX[4], MY[4];
    #pragma unroll
    for (int r = 0; r < 4; r++) {
        const int of = min(c.i0 + c.dy2 + r, HH - 1) * WW;
        ldpair<Q>(c.mk + of, cB0, MX[r], MY[r]);
    }

    const float jv0 = (c.j0     < c.jmax) ? 1.0f : 0.0f;
    const float jv1 = (c.j0 + 1 < c.jmax) ? 1.0f : 0.0f;

    float acc = 0.0f;
    #pragma unroll
    for (int r = 0; r < 4; r++) {
        const int of = min(c.i0 + c.dy2 + r, HH - 1) * WW;
        float2 v0 = ld2(c.g0 + of + c.j0);
        float2 v1 = ld2(c.g1 + of + c.j0);
        float z0 = c.g0[of + min(c.j0 + 2, WW - 1)];
        float z1 = c.g1[of + min(c.j0 + 2, WW - 1)];
        const float rvv = (c.i0 + r < c.imax) ? 1.0f : 0.0f;
        const float wmx = MX[r] * rvv * jv0;
        const float wmy = MY[r] * rvv * jv1;
        float Hx = c.sy * v0.x + c.sx * v1.x;
        float Hy = c.sy * v0.y + c.sx * v1.y;
        float Hz = c.sy * z0   + c.sx * z1;
        float f0 = c.wx1 * Hx + c.wx2 * Hy;
        float s0 = c.wy1 * Sa[r+1] + c.wy2 * Sa[r];
        float e0 = f0 - s0;
        acc += wmx * e0 * e0;
        float f1 = c.wx1 * Hy + c.wx2 * Hz;
        float s1 = c.wy1 * Sb[r+1] + c.wy2 * Sb[r];
        float e1 = f1 - s1;
        acc += wmy * e1 * e1;
    }
    return acc;
}

__global__ __launch_bounds__(256, 5)
void loss_kernel(const float* __restrict__ grid,
                 const float* __restrict__ gt,
                 const float* __restrict__ gd,
                 const float* __restrict__ mask,
                 int B, unsigned int units, float* __restrict__ out)
{
    const int H = HH, W = WW;
    const int tid = threadIdx.x;

    __shared__ float wsum[8];

    float facc = 0.0f;

    // static assignment; warps proceed fully independently (no shared state)
    for (unsigned int u = blockIdx.x; u < units; u += gridDim.x) {
        const int b  = (int)(u >> 7);         // 128 strips per batch item
        const int i0 = (int)(u & 127u) * 4;

        const float dx = -8.0f * gt[2 * b + 0];
        const float dy =  8.0f * gt[2 * b + 1];

        Ctx c;
        c.sx = gd[2 * b + 0];
        c.sy = gd[2 * b + 1];
        const float dx1f = floorf(dx), dy1f = floorf(dy);
        c.dx1 = (int)dx1f;  c.dy1 = (int)dy1f;  c.dy2 = c.dy1 + 1;
        const int dx2 = c.dx1 + 1;
        c.wx1 = (dx1f + 1.0f) - dx;  c.wx2 = dx - dx1f;
        c.wy1 = (dy1f + 1.0f) - dy;  c.wy2 = dy - dy1f;
        c.w11 = c.wy1 * c.wx1;  c.w12 = c.wy1 * c.wx2;
        c.w21 = c.wy2 * c.wx1;  c.w22 = c.wy2 * c.wx2;
        c.g0 = grid + (size_t)(2 * b + 0) * H * W;
        c.g1 = grid + (size_t)(2 * b + 1) * H * W;
        c.mk = mask + (size_t)b * H * W;
        c.imax = H - c.dy2;
        c.i0 = i0;
        c.j0 = 2 * tid;

        float uacc;
        float cnt;
        if (dx > 0.0f) {
            c.jmax = W - dx2;
            cnt = (float)c.imax * (float)c.jmax;
            if (c.dx1 & 1) uacc = pos_quad<1>(c);
            else           uacc = pos_quad<0>(c);
        } else {
            c.jmax = W + c.dx1;
            cnt = (float)c.imax * (float)c.jmax;
            if ((-c.dx1) & 1) uacc = neg_quad<1>(c);
            else              uacc = neg_quad<0>(c);
        }
        facc += __fdividef(uacc, cnt);
    }

    // ---- block reduction (8 warps)
    #pragma unroll
    for (int o = 16; o > 0; o >>= 1)
        facc += __shfl_down_sync(0xFFFFFFFFu, facc, o);

    const int lane = tid & 31;
    const int warp = tid >> 5;
    if (lane == 0) wsum[warp] = facc;
    __syncthreads();

    if (tid == 0) {
        float s = 0.0f;
        #pragma unroll
        for (int k = 0; k < 8; k++) s += wsum[k];
        atomicAdd(&g_acc, (double)s);

        __threadfence();
        unsigned int prev = atomicInc(&g_ticket, (unsigned int)gridDim.x - 1u);
        if (prev == (unsigned int)gridDim.x - 1u) {
            double total = atomicAdd(&g_acc, 0.0);    // atomic read
            out[0] = (float)(total / (double)B);
            g_acc  = 0.0;                             // reset for next replay
            __threadfence();
        }
    }
}

extern "C" void kernel_launch(void* const* d_in, const int* in_sizes, int n_in,
                              void* d_out, int out_size)
{
    const float* grid = (const float*)d_in[0];
    const float* gt   = (const float*)d_in[1];
    const float* gd   = (const float*)d_in[2];
    const float* mask = (const float*)d_in[3];
    float* out = (float*)d_out;

    const int B = in_sizes[1] / 2;            // gt_sym_axis is (B, 2)
    const unsigned int units = (unsigned int)(128 * B);

    loss_kernel<<<NPERSIST, 256>>>(grid, gt, gd, mask, B, units, out);
}